// round 8
// baseline (speedup 1.0000x reference)
#include <cuda_runtime.h>
#include <cuda_fp16.h>

// Problem constants
#define KCLS  256
#define NTOT  24000              // BS*Q rows
#define TTOT  2400               // targets
#define NQUAD (TTOT / 4)         // 600 quads of 4 targets
#define TPB   128
#define NBLK  2664               // 148 SMs x 9 blocks x 2 = EXACTLY two waves
#define RMAX  10                 // 24 blocks w/ 10 rows + 2640 w/ 9 = 24000

// Precomputed x5-scaled target splats, SoA for coalesced LDG.128 by quad q:
//  g_t0[q]: cxcywh half2 (targets {4q,4q+1});  g_t1[q]: xyxy half2 (same pair)
//  g_t2[q]: cxcywh half2 (targets {4q+2,4q+3}); g_t3[q]: xyxy half2 (same pair)
//  g_t4[q]: (area2 pair0, area2 pair1) as half2-in-float
__device__ float4 g_t0[NQUAD], g_t1[NQUAD], g_t2[NQUAD], g_t3[NQUAD];
__device__ float2 g_t4[NQUAD];

static __device__ __forceinline__ half2 h2_from_f(float f) {
    return *reinterpret_cast<half2*>(&f);
}
static __device__ __forceinline__ float f_from_h2(half2 h) {
    return *reinterpret_cast<float*>(&h);
}

// ---------------------------------------------------------------------------
// Kernel T: one-time target splat precompute (x5-scaled, half2-packed)
// ---------------------------------------------------------------------------
__global__ __launch_bounds__(128) void tprep_kernel(const float* __restrict__ tgt_bbox)
{
    int q = blockIdx.x * 128 + threadIdx.x;
    if (q >= NQUAD) return;
    float2 ar;
    #pragma unroll
    for (int g = 0; g < 2; g++) {
        float4 a  = reinterpret_cast<const float4*>(tgt_bbox)[4 * q + 2 * g];
        float4 bx = reinterpret_cast<const float4*>(tgt_bbox)[4 * q + 2 * g + 1];
        a.x *= 5.0f;  a.y *= 5.0f;  a.z *= 5.0f;  a.w *= 5.0f;
        bx.x *= 5.0f; bx.y *= 5.0f; bx.z *= 5.0f; bx.w *= 5.0f;
        float4 c4 = make_float4(
            f_from_h2(__floats2half2_rn(a.x, bx.x)),
            f_from_h2(__floats2half2_rn(a.y, bx.y)),
            f_from_h2(__floats2half2_rn(a.z, bx.z)),
            f_from_h2(__floats2half2_rn(a.w, bx.w)));
        float4 x4 = make_float4(
            f_from_h2(__floats2half2_rn(a.x - 0.5f * a.z, bx.x - 0.5f * bx.z)),
            f_from_h2(__floats2half2_rn(a.y - 0.5f * a.w, bx.y - 0.5f * bx.w)),
            f_from_h2(__floats2half2_rn(a.x + 0.5f * a.z, bx.x + 0.5f * bx.z)),
            f_from_h2(__floats2half2_rn(a.y + 0.5f * a.w, bx.y + 0.5f * bx.w)));
        if (g == 0) { g_t0[q] = c4; g_t1[q] = x4; }
        else        { g_t2[q] = c4; g_t3[q] = x4; }
        (&ar.x)[g] = f_from_h2(__floats2half2_rn(a.z * a.w, bx.z * bx.w));
    }
    g_t4[q] = ar;
}

// ---------------------------------------------------------------------------
// Fused kernel, two exact waves; block b owns rows [n0, n0+R), R in {9,10}
// ---------------------------------------------------------------------------
__global__ __launch_bounds__(TPB, 9) void fused_kernel(
    const float* __restrict__ logits,       // [NTOT, 256]
    const float* __restrict__ pred_boxes,   // [NTOT, 4] cxcywh
    const int*   __restrict__ tgt_ids,      // [TTOT]
    float*       __restrict__ out)          // [NTOT, TTOT]
{
    __shared__ float4 s_diff4[RMAX * KCLS / 4];    // 10240 B
    __shared__ float4 s_pd[RMAX][2];               //   320 B (cxcywh h2, xyxy h2)

    const int tid = threadIdx.x;
    const int b   = blockIdx.x;
    const int n0  = b * 9 + min(b, 24);
    const int R   = (b < 24) ? 10 : 9;

    // ---- preamble A: class-cost table for R rows: focal(pos-neg)+2
    const float4* lg4 = reinterpret_cast<const float4*>(logits) + n0 * (KCLS / 4);
    for (int i = tid; i < R * (KCLS / 4); i += TPB) {
        float4 x4 = lg4[i];
        float4 o4;
        const float* xs = &x4.x;
        float*       os = &o4.x;
        #pragma unroll
        for (int j = 0; j < 4; j++) {
            float x   = xs[j];
            float ex  = __expf(-x);
            float L   = __logf(1.0f + ex);                // = -log(p)
            float p   = __frcp_rn(1.0f + ex);
            float omp = 1.0f - p;
            float pos = 0.25f * omp * omp * L;            // A(1-p)^2 * -log p
            float neg = 0.75f * p * p * (x + L);          // (1-A) p^2 * -log(1-p)
            os[j] = pos - neg + 2.0f;                     // +2 folds GIoU constant
        }
        s_diff4[i] = o4;
    }

    // ---- preamble B: pred boxes -> x5-scaled half2 splats (area derived later)
    if (tid < R) {
        float4 pb = reinterpret_cast<const float4*>(pred_boxes)[n0 + tid];
        pb.x *= 5.0f; pb.y *= 5.0f; pb.z *= 5.0f; pb.w *= 5.0f;
        s_pd[tid][0] = make_float4(f_from_h2(__float2half2_rn(pb.x)),
                                   f_from_h2(__float2half2_rn(pb.y)),
                                   f_from_h2(__float2half2_rn(pb.z)),
                                   f_from_h2(__float2half2_rn(pb.w)));
        s_pd[tid][1] = make_float4(f_from_h2(__float2half2_rn(pb.x - 0.5f * pb.z)),
                                   f_from_h2(__float2half2_rn(pb.y - 0.5f * pb.w)),
                                   f_from_h2(__float2half2_rn(pb.x + 0.5f * pb.z)),
                                   f_from_h2(__float2half2_rn(pb.y + 0.5f * pb.w)));
    }
    __syncthreads();

    const float* s_diff = reinterpret_cast<const float*>(s_diff4);
    const half2 zero2 = __float2half2_rn(0.0f);
    const half2 m2    = __float2half2_rn(-2.0f);

    for (int q = tid; q < NQUAD; q += TPB) {
        // ---- precomputed target splats (coalesced LDG, L2-hot) ----
        int4 id4 = reinterpret_cast<const int4*>(tgt_ids)[q];
        const int ids[4] = {id4.x, id4.y, id4.z, id4.w};
        float4 tc[2], tx[2];
        tc[0] = g_t0[q];  tx[0] = g_t1[q];
        tc[1] = g_t2[q];  tx[1] = g_t3[q];
        float2 tar = g_t4[q];

        #pragma unroll 1
        for (int r = 0; r < R; r++) {
            const float4 f0 = s_pd[r][0];                 // 2x LDS.128 broadcast
            const float4 f1 = s_pd[r][1];
            const half2 pcx2  = h2_from_f(f0.x);
            const half2 pcy2  = h2_from_f(f0.y);
            const half2 pw2   = h2_from_f(f0.z);
            const half2 ph2   = h2_from_f(f0.w);
            const half2 px0_2 = h2_from_f(f1.x);
            const half2 py0_2 = h2_from_f(f1.y);
            const half2 px1_2 = h2_from_f(f1.z);
            const half2 py1_2 = h2_from_f(f1.w);
            const half2 pa_2  = __hmul2(pw2, ph2);        // replaces 3rd LDS
            const float* __restrict__ drow = s_diff + r * KCLS;

            float hv[4];
            #pragma unroll
            for (int g = 0; g < 2; g++) {
                const half2 tcx2 = h2_from_f(tc[g].x);
                const half2 tcy2 = h2_from_f(tc[g].y);
                const half2 tw2  = h2_from_f(tc[g].z);
                const half2 th2  = h2_from_f(tc[g].w);
                const half2 tx02 = h2_from_f(tx[g].x);
                const half2 ty02 = h2_from_f(tx[g].y);
                const half2 tx12 = h2_from_f(tx[g].z);
                const half2 ty12 = h2_from_f(tx[g].w);
                const half2 ta2  = h2_from_f((&tar.x)[g]);
                // ---- 5*L1 (x5-scaled coords) ----
                half2 l15 = __hadd2(
                    __hadd2(__habs2(__hsub2(pcx2, tcx2)),
                            __habs2(__hsub2(pcy2, tcy2))),
                    __hadd2(__habs2(__hsub2(pw2,  tw2)),
                            __habs2(__hsub2(ph2,  th2))));
                // ---- GIoU (scale-invariant) ----
                half2 diw = __hsub2(__hmin2(px1_2, tx12), __hmax2(px0_2, tx02));
                half2 dih = __hsub2(__hmin2(py1_2, ty12), __hmax2(py0_2, ty02));
                half2 inter = __hmul2(__hmax2(diw, zero2), __hmax2(dih, zero2));
                half2 uni   = __hsub2(__hadd2(pa_2, ta2), inter);
                half2 ew  = __hsub2(__hadd2(pw2, tw2), diw);
                half2 eh  = __hsub2(__hadd2(ph2, th2), dih);
                half2 ea  = __hmul2(ew, eh);
                half2 tm  = __hfma2(uni, h2rcp(ea), __hmul2(inter, h2rcp(uni)));
                // ---- fused: h = 5*L1 - 2*(i/u + u/e) ----
                half2 h = __hfma2(tm, m2, l15);
                hv[2 * g]     = __low2float(h);
                hv[2 * g + 1] = __high2float(h);
            }

            float c[4];
            #pragma unroll
            for (int j = 0; j < 4; j++)
                c[j] = hv[j] + drow[ids[j]];              // + (diff+2) fp32
            reinterpret_cast<float4*>(out)[(n0 + r) * NQUAD + q] =
                make_float4(c[0], c[1], c[2], c[3]);
        }
    }
}

// ---------------------------------------------------------------------------
extern "C" void kernel_launch(void* const* d_in, const int* in_sizes, int n_in,
                              void* d_out, int out_size)
{
    const float* pred_logits = (const float*)d_in[0];  // [16,1500,256]
    const float* pred_boxes  = (const float*)d_in[1];  // [16,1500,4]
    const float* tgt_bbox    = (const float*)d_in[2];  // [2400,4]
    const int*   tgt_ids     = (const int*)  d_in[3];  // [2400]
    float*       out         = (float*)d_out;          // [16,1500,2400]

    tprep_kernel<<<(NQUAD + 127) / 128, 128>>>(tgt_bbox);
    fused_kernel<<<NBLK, TPB>>>(pred_logits, pred_boxes, tgt_ids, out);
}